// round 9
// baseline (speedup 1.0000x reference)
#include <cuda_runtime.h>
#include <cuda_fp16.h>
#include <math.h>

#define B_SZ 2
#define N_SZ 512
#define EDIM 64
#define NDIM 256
#define HEADS 8
#define DH 32
#define SCALE_F 0.17677669529663687f  // 1/sqrt(32)

// ---------------- scratch (device globals; no allocation allowed) ----------------
__device__ float g_qc[B_SZ * N_SZ * NDIM];   // nq + beq
__device__ float g_kc[B_SZ * N_SZ * NDIM];   // nk + bek
__device__ float g_vc[B_SZ * N_SZ * NDIM];   // nv + bev
__device__ float g_att[B_SZ * HEADS * N_SZ * N_SZ];  // unnormalized softmax (16MB)
__device__ float g_ce[B_SZ * N_SZ * HEADS * EDIM];   // ctx_e per (b,i,h,64)
__device__ float g_ssum[B_SZ * N_SZ * HEADS];        // softmax denominators
__device__ uint2 g_wfq16[4096];  // fp16 fragment-ordered Weq [h][ni][ks][lane]
__device__ uint2 g_wfk16[4096];  // fp16 fragment-ordered Wek
__device__ float g_po[B_SZ * HEADS * 4 * N_SZ * DH]; // att@vc partials [b][h][jq][i][d]

// ---------------- helpers ----------------
__device__ __forceinline__ unsigned f2tf(float f) {
    unsigned u; asm("cvt.rna.tf32.f32 %0, %1;" : "=r"(u) : "f"(f)); return u;
}
__device__ __forceinline__ unsigned pack_h2(float x, float y) {
    __half2 h = __floats2half2_rn(x, y);
    return *(unsigned*)&h;
}
__device__ __forceinline__ void mma_tf32(float* d, const unsigned* a, const unsigned* b) {
    asm("mma.sync.aligned.m16n8k8.row.col.f32.tf32.tf32.f32 "
        "{%0,%1,%2,%3}, {%4,%5,%6,%7}, {%8,%9}, {%0,%1,%2,%3};"
        : "+f"(d[0]), "+f"(d[1]), "+f"(d[2]), "+f"(d[3])
        : "r"(a[0]), "r"(a[1]), "r"(a[2]), "r"(a[3]), "r"(b[0]), "r"(b[1]));
}
__device__ __forceinline__ void mma_f16(float* d, const unsigned* a, const unsigned* b) {
    asm("mma.sync.aligned.m16n8k16.row.col.f32.f16.f16.f32 "
        "{%0,%1,%2,%3}, {%4,%5,%6,%7}, {%8,%9}, {%0,%1,%2,%3};"
        : "+f"(d[0]), "+f"(d[1]), "+f"(d[2]), "+f"(d[3])
        : "r"(a[0]), "r"(a[1]), "r"(a[2]), "r"(a[3]), "r"(b[0]), "r"(b[1]));
}
__device__ __forceinline__ void cp_async16(void* smem_dst, const void* gsrc) {
    unsigned s = (unsigned)__cvta_generic_to_shared(smem_dst);
    asm volatile("cp.async.cg.shared.global [%0], [%1], 16;" :: "r"(s), "l"(gsrc));
}

// =================================================================================
// Kernel W: build fp16 fragment-ordered weight tables.
// =================================================================================
__global__ __launch_bounds__(256) void weight_frag_kernel(
    const float* __restrict__ Weq, const float* __restrict__ Wek)
{
    int idx = blockIdx.x * 256 + threadIdx.x;   // 0..4095
    if (idx >= 4096) return;
    int l  = idx & 31;
    int ks = (idx >> 5) & 3;
    int ni = (idx >> 7) & 3;
    int hh = idx >> 9;
    int gg = l >> 2, cc = l & 3;
    int wrow = hh * 32 + ni * 8 + gg;
    const float* wq = Weq + wrow * 64 + ks * 16;
    const float* wk = Wek + wrow * 64 + ks * 16;
    g_wfq16[idx] = make_uint2(pack_h2(wq[2*cc], wq[2*cc+1]), pack_h2(wq[2*cc+8], wq[2*cc+9]));
    g_wfk16[idx] = make_uint2(pack_h2(wk[2*cc], wk[2*cc+1]), pack_h2(wk[2*cc+8], wk[2*cc+9]));
}

// =================================================================================
// Kernel A: node projections. grid (64, 3), 16 rows/CTA.
// =================================================================================
__global__ __launch_bounds__(256) void node_proj_kernel(
    const float* __restrict__ node,
    const float* __restrict__ Wnq, const float* __restrict__ bnq,
    const float* __restrict__ Wnk, const float* __restrict__ bnk,
    const float* __restrict__ Wnv, const float* __restrict__ bnv,
    const float* __restrict__ beq, const float* __restrict__ bek,
    const float* __restrict__ bev)
{
    extern __shared__ float smA[];
    float* node_s = smA;              // 16*257
    float* wt     = smA + 16 * 257;   // 64*260

    const int tid = threadIdx.x;
    const int r  = tid & 15;
    const int cg = tid >> 4;
    const int r0 = blockIdx.x * 16;
    const int p  = blockIdx.y;

    const float* W  = (p == 0) ? Wnq : (p == 1) ? Wnk : Wnv;
    const float* b1 = (p == 0) ? bnq : (p == 1) ? bnk : bnv;
    const float* b2 = (p == 0) ? beq : (p == 1) ? bek : bev;
    float* dst = (p == 0) ? g_qc : (p == 1) ? g_kc : g_vc;

    for (int idx = tid; idx < 16 * 256; idx += 256) {
        int rr = idx >> 8, k = idx & 255;
        node_s[rr * 257 + k] = node[(r0 + rr) * 256 + k];
    }

    float acc[16];
    #pragma unroll
    for (int q = 0; q < 16; q++) acc[q] = 0.f;

    for (int kt = 0; kt < 4; kt++) {
        __syncthreads();
        for (int idx = tid; idx < 64 * 256; idx += 256) {
            int c = idx >> 6, kk = idx & 63;
            wt[kk * 260 + c] = W[c * 256 + kt * 64 + kk];
        }
        __syncthreads();
        #pragma unroll 4
        for (int kk = 0; kk < 64; kk++) {
            float nv = node_s[r * 257 + kt * 64 + kk];
            const float* wrow = &wt[kk * 260 + cg * 16];
            float4 w0 = *(const float4*)(wrow);
            float4 w1 = *(const float4*)(wrow + 4);
            float4 w2 = *(const float4*)(wrow + 8);
            float4 w3 = *(const float4*)(wrow + 12);
            acc[0]  += w0.x * nv; acc[1]  += w0.y * nv; acc[2]  += w0.z * nv; acc[3]  += w0.w * nv;
            acc[4]  += w1.x * nv; acc[5]  += w1.y * nv; acc[6]  += w1.z * nv; acc[7]  += w1.w * nv;
            acc[8]  += w2.x * nv; acc[9]  += w2.y * nv; acc[10] += w2.z * nv; acc[11] += w2.w * nv;
            acc[12] += w3.x * nv; acc[13] += w3.y * nv; acc[14] += w3.z * nv; acc[15] += w3.w * nv;
        }
    }
    int row = r0 + r;
    #pragma unroll
    for (int q4 = 0; q4 < 4; q4++) {
        float4 bb1 = *(const float4*)&b1[cg * 16 + q4 * 4];
        float4 bb2 = *(const float4*)&b2[cg * 16 + q4 * 4];
        float4 v;
        v.x = acc[q4 * 4 + 0] + bb1.x + bb2.x;
        v.y = acc[q4 * 4 + 1] + bb1.y + bb2.y;
        v.z = acc[q4 * 4 + 2] + bb1.z + bb2.z;
        v.w = acc[q4 * 4 + 3] + bb1.w + bb2.w;
        *(float4*)&dst[row * 256 + cg * 16 + q4 * 4] = v;
    }
}

// =================================================================================
// Kernel B: per (b,i) CTA, 256 threads = 8 warps (warp = head), 46.9KB smem.
// Phase 1 only: fp16 mma for qk + ONLINE softmax + online ctx_e accumulation
// (tf32 mma on the same resident edge tile). No phase-2 re-staging.
// =================================================================================
__global__ __launch_bounds__(256, 2) void attn_kernel(
    const float* __restrict__ edge)
{
    extern __shared__ float sm[];
    float* sQK = sm;              // 8 x 516 = 4128 (raw scaled qk)
    float* sQC = sm + 4128;       // 256
    float* sCE = sm + 4384;       // 512 (final ctx_e staging)
    float* sPt = sm + 4896;       // 8 x 36 = 288 (per-tile p values)
    float* sSc = sm + 5184;       // 8 (per-head rescale factors)
    float* sE  = sm + 5192;       // 3 x 2176 edge tile ring (32j x 68)
    // total 11720 floats = 46880 bytes

    const int i = blockIdx.x;
    const int b = blockIdx.y;
    const int tid = threadIdx.x;
    const int lane = tid & 31;
    const int h = tid >> 5;      // warp = head (also = d-slice for ctx mma)
    const int g = lane >> 2;     // 0..7
    const int c = lane & 3;

    const int bN = b * N_SZ;
    const float* edgeRowBase = edge + (size_t)(bN + i) * N_SZ * EDIM;

    // ---- start cp.async of tile 0 ----
    {
        const float4* src = (const float4*)(edgeRowBase);
        #pragma unroll
        for (int u = 0; u < 2; u++) {
            int idx = tid + u * 256;
            int row = idx >> 4, q = idx & 15;
            cp_async16(sE + row * 68 + q * 4, src + idx);
        }
        asm volatile("cp.async.commit_group;");
    }
    sQC[tid] = g_qc[(bN + i) * NDIM + tid];

    float Dc[4] = {0.f, 0.f, 0.f, 0.f};   // online ctx_e accumulator
    float m_run = -1e30f;

    // ---------------- fused phase: qk + online softmax + ctx_e ----------------
    for (int jt = 0; jt < 16; jt++) {
        if (jt < 15) {
            const float4* src = (const float4*)(edgeRowBase + (jt + 1) * 32 * EDIM);
            float* dstb = sE + ((jt + 1) % 3) * 2176;
            #pragma unroll
            for (int u = 0; u < 2; u++) {
                int idx = tid + u * 256;
                int row = idx >> 4, q = idx & 15;
                cp_async16(dstb + row * 68 + q * 4, src + idx);
            }
            asm volatile("cp.async.commit_group;");
            asm volatile("cp.async.wait_group 1;");
        } else {
            asm volatile("cp.async.wait_group 0;");
        }
        __syncthreads();   // SYNC_A: tile jt visible; prev tile's ctx reads done

        const float* eb = sE + (jt % 3) * 2176;
        const int jg0 = jt * 32;

        // ---- qk via fp16 mma ----
        float Dq[2][4][4], Dk[2][4][4];
        #pragma unroll
        for (int mi = 0; mi < 2; mi++)
            #pragma unroll
            for (int ni = 0; ni < 4; ni++)
                #pragma unroll
                for (int e = 0; e < 4; e++) { Dq[mi][ni][e] = 0.f; Dk[mi][ni][e] = 0.f; }

        #pragma unroll
        for (int ks = 0; ks < 4; ks++) {
            const int col = ks * 16 + 2 * c;
            unsigned a0[4], a1[4];
            {
                float2 e;
                e = *(const float2*)&eb[g * 68 + col];            a0[0] = pack_h2(e.x, e.y);
                e = *(const float2*)&eb[(g + 8) * 68 + col];      a0[1] = pack_h2(e.x, e.y);
                e = *(const float2*)&eb[g * 68 + col + 8];        a0[2] = pack_h2(e.x, e.y);
                e = *(const float2*)&eb[(g + 8) * 68 + col + 8];  a0[3] = pack_h2(e.x, e.y);
                e = *(const float2*)&eb[(g + 16) * 68 + col];     a1[0] = pack_h2(e.x, e.y);
                e = *(const float2*)&eb[(g + 24) * 68 + col];     a1[1] = pack_h2(e.x, e.y);
                e = *(const float2*)&eb[(g + 16) * 68 + col + 8]; a1[2] = pack_h2(e.x, e.y);
                e = *(const float2*)&eb[(g + 24) * 68 + col + 8]; a1[3] = pack_h2(e.x, e.y);
            }
            #pragma unroll
            for (int ni = 0; ni < 4; ni++) {
                const int wi = ((h * 4 + ni) * 4 + ks) * 32 + lane;
                uint2 bq = __ldg(&g_wfq16[wi]);
                uint2 bk = __ldg(&g_wfk16[wi]);
                mma_f16(Dq[0][ni], a0, (const unsigned*)&bq);
                mma_f16(Dq[1][ni], a1, (const unsigned*)&bq);
                mma_f16(Dk[0][ni], a0, (const unsigned*)&bk);
                mma_f16(Dk[1][ni], a1, (const unsigned*)&bk);
            }
        }

        // ---- combine: qk[j] = sum_d (EQ+qc)(EK+kc) ----
        float acc[4] = {0.f, 0.f, 0.f, 0.f};
        #pragma unroll
        for (int mi = 0; mi < 2; mi++) {
            int r0 = mi * 16 + g;
            #pragma unroll
            for (int ni = 0; ni < 4; ni++) {
                int ch = h * 32 + ni * 8 + 2 * c;
                float q0 = sQC[ch], q1 = sQC[ch + 1];
                float2 kA = __ldg((const float2*)(g_kc + (size_t)(bN + jg0 + r0) * NDIM + ch));
                float2 kB = __ldg((const float2*)(g_kc + (size_t)(bN + jg0 + r0 + 8) * NDIM + ch));
                acc[mi * 2]     += (Dq[mi][ni][0] + q0) * (Dk[mi][ni][0] + kA.x)
                                 + (Dq[mi][ni][1] + q1) * (Dk[mi][ni][1] + kA.y);
                acc[mi * 2 + 1] += (Dq[mi][ni][2] + q0) * (Dk[mi][ni][2] + kB.x)
                                 + (Dq[mi][ni][3] + q1) * (Dk[mi][ni][3] + kB.y);
            }
        }
        #pragma unroll
        for (int t = 1; t <= 2; t <<= 1) {
            acc[0] += __shfl_xor_sync(0xffffffffu, acc[0], t);
            acc[1] += __shfl_xor_sync(0xffffffffu, acc[1], t);
            acc[2] += __shfl_xor_sync(0xffffffffu, acc[2], t);
            acc[3] += __shfl_xor_sync(0xffffffffu, acc[3], t);
        }

        // ---- online softmax bookkeeping (all lanes consistent across c) ----
        float qs0 = acc[0] * SCALE_F, qs1 = acc[1] * SCALE_F;
        float qs2 = acc[2] * SCALE_F, qs3 = acc[3] * SCALE_F;
        float tm = fmaxf(fmaxf(qs0, qs1), fmaxf(qs2, qs3));
        #pragma unroll
        for (int off = 4; off <= 16; off <<= 1)
            tm = fmaxf(tm, __shfl_xor_sync(0xffffffffu, tm, off));
        float m_new = fmaxf(m_run, tm);
        float sc = __expf(m_run - m_new);
        float p0 = __uint_as_float(f2tf(__expf(qs0 - m_new)));
        float p1 = __uint_as_float(f2tf(__expf(qs1 - m_new)));
        float p2 = __uint_as_float(f2tf(__expf(qs2 - m_new)));
        float p3 = __uint_as_float(f2tf(__expf(qs3 - m_new)));
        m_run = m_new;

        if (c == 0) {
            sQK[h * 516 + jg0 + g]      = qs0;
            sQK[h * 516 + jg0 + g + 8]  = qs1;
            sQK[h * 516 + jg0 + 16 + g] = qs2;
            sQK[h * 516 + jg0 + 24 + g] = qs3;
            sPt[h * 36 + g]      = p0;
            sPt[h * 36 + g + 8]  = p1;
            sPt[h * 36 + 16 + g] = p2;
            sPt[h * 36 + 24 + g] = p3;
            if (lane == 0) sSc[h] = sc;
        }
        __syncthreads();   // SYNC_B: p-tile + scales visible

        // ---- online ctx_e: rescale then accumulate p @ E (tf32 mma) ----
        {
            float f = sSc[g];
            Dc[0] *= f; Dc[1] *= f; Dc[2] *= f; Dc[3] *= f;
            #pragma unroll
            for (int ks2 = 0; ks2 < 4; ks2++) {
                const int jl = ks2 * 8;
                unsigned aa[4], bb[2];
                aa[0] = __float_as_uint(sPt[g * 36 + jl + c]);
                aa[1] = 0u;
                aa[2] = __float_as_uint(sPt[g * 36 + jl + c + 4]);
                aa[3] = 0u;
                bb[0] = __float_as_uint(eb[(jl + c) * 68 + h * 8 + g]);
                bb[1] = __float_as_uint(eb[(jl + c + 4) * 68 + h * 8 + g]);
                mma_tf32(Dc, aa, bb);
            }
        }
    }

    // ---------------- softmax export (warp h owns its own row; m_run is final max)
    {
        float* srow = sQK + h * 516;
        float* gatt = g_att + ((size_t)(b * HEADS + h) * N_SZ + i) * N_SZ;
        float ssum = 0.f;
        for (int jj = lane; jj < 512; jj += 32) {
            float pr = __uint_as_float(f2tf(__expf(srow[jj] - m_run)));
            gatt[jj] = pr;
            ssum += pr;
        }
        #pragma unroll
        for (int off = 16; off > 0; off >>= 1) ssum += __shfl_xor_sync(0xffffffffu, ssum, off);
        if (lane == 0) g_ssum[(size_t)(bN + i) * HEADS + h] = ssum;
    }

    // ---------------- ctx_e write: lane (g,c) of warp h holds head g, cols h*8+2c
    sCE[g * 64 + h * 8 + 2 * c]     = Dc[0];
    sCE[g * 64 + h * 8 + 2 * c + 1] = Dc[1];
    __syncthreads();
    g_ce[(size_t)(bN + i) * 512 + tid]       = sCE[tid];
    g_ce[(size_t)(bN + i) * 512 + 256 + tid] = sCE[256 + tid];
}

// =================================================================================
// Kernel C1: att@vc partials. grid (32 = jq*8+it, 8, 2), 256 threads, 16KB smem.
// =================================================================================
__global__ __launch_bounds__(256) void outp_kernel()
{
    __shared__ float svc[128 * 32];

    const int x  = blockIdx.x;
    const int jq = x >> 3;
    const int it = x & 7;
    const int h  = blockIdx.y;
    const int b  = blockIdx.z;
    const int tid = threadIdx.x;
    const int ti = tid >> 5;
    const int lane = tid & 31;
    const int j0 = jq * 128;

    for (int idx = tid; idx < 128 * 8; idx += 256) {
        int j = idx >> 3, q = idx & 7;
        float4 v = __ldg((const float4*)&g_vc[(size_t)(b * N_SZ + j0 + j) * NDIM + h * 32 + q * 4]);
        *(float4*)&svc[j * 32 + q * 4] = v;
    }
    __syncthreads();

    #pragma unroll
    for (int half = 0; half < 2; half++) {
        const int i0 = it * 64 + ti * 8 + half * 4;
        const float* arow = g_att + ((size_t)(b * HEADS + h) * N_SZ + i0) * N_SZ + j0;
        float acc0 = 0.f, acc1 = 0.f, acc2 = 0.f, acc3 = 0.f;
        #pragma unroll 4
        for (int j = 0; j < 128; j += 4) {
            float4 a0 = __ldg((const float4*)(arow + j));
            float4 a1 = __ldg((const float4*)(arow + 512 + j));
            float4 a2 = __ldg((const float4*)(arow + 1024 + j));
            float4 a3 = __ldg((const float4*)(arow + 1536 + j));
            float v0 = svc[(j + 0) * 32 + lane];
            float v1 = svc[(j + 1) * 32 + lane];
            float v2 = svc[(j + 2) * 32 + lane];
            float v3 = svc[(j + 3) * 32 + lane];
            acc0 += a0.x * v0 + a0.y * v1 + a0.z * v2 + a0.w * v3;
            acc1 += a1.x * v0 + a1.y * v1 + a1.z * v2 + a1.w * v3;
            acc2 += a2.x * v0 + a2.y * v1 + a2.z * v2 + a2.w * v3;
            acc3 += a3.x * v0 + a3.y * v1 + a3.z * v2 + a3.w * v3;
        }
        float* po = g_po + (((size_t)(b * HEADS + h) * 4 + jq) * N_SZ + i0) * DH + lane;
        po[0 * DH] = acc0;
        po[1 * DH] = acc1;
        po[2 * DH] = acc2;
        po[3 * DH] = acc3;
    }
}

// =================================================================================
// Kernel C2: reduce partials + Wev·ctx_e epilogue. grid (8, 8, 2), 256 threads.
// =================================================================================
__global__ __launch_bounds__(256) void outr_kernel(
    const float* __restrict__ Wev,
    float* __restrict__ out)
{
    __shared__ float sWev[32 * 65];
    __shared__ float sCe[64 * 64];

    const int it = blockIdx.x;
    const int h  = blockIdx.y;
    const int b  = blockIdx.z;
    const int tid = threadIdx.x;
    const int ti = tid >> 5;
    const int lane = tid & 31;

    for (int idx = tid; idx < 2048; idx += 256) {
        int row = idx >> 6, dp = idx & 63;
        sWev[row * 65 + dp] = __ldg(&Wev[(h * 32 + row) * 64 + dp]);
    }
    for (int idx = tid; idx < 64 * 16; idx += 256) {
        int il = idx >> 4, q = idx & 15;
        float4 v = __ldg((const float4*)&g_ce[(size_t)(b * N_SZ + it * 64 + il) * 512 + h * 64 + q * 4]);
        *(float4*)&sCe[il * 64 + q * 4] = v;
    }
    __syncthreads();

    #pragma unroll
    for (int ii = 0; ii < 8; ii++) {
        int il = ti * 8 + ii;
        int ig = it * 64 + il;
        float a = 0.f;
        #pragma unroll
        for (int jq = 0; jq < 4; jq++)
            a += __ldg(&g_po[(((size_t)(b * HEADS + h) * 4 + jq) * N_SZ + ig) * DH + lane]);
        float dot = 0.f;
        #pragma unroll 8
        for (int dp = 0; dp < 64; dp++)
            dot += sCe[il * 64 + dp] * sWev[lane * 65 + dp];
        float inv = 1.f / __ldg(&g_ssum[(size_t)(b * N_SZ + ig) * HEADS + h]);
        out[(size_t)(b * N_SZ + ig) * NDIM + h * 32 + lane] = (dot + a) * inv;
    }
}

// =================================================================================
extern "C" void kernel_launch(void* const* d_in, const int* in_sizes, int n_in,
                              void* d_out, int out_size)
{
    const float* node = (const float*)d_in[0];
    const float* edge = (const float*)d_in[1];
    const float* Wnq  = (const float*)d_in[2];
    const float* bnq  = (const float*)d_in[3];
    const float* Wnk  = (const float*)d_in[4];
    const float* bnk  = (const float*)d_in[5];
    const float* Wnv  = (const float*)d_in[6];
    const float* bnv  = (const float*)d_in[7];
    const float* Weq  = (const float*)d_in[8];
    const float* beq  = (const float*)d_in[9];
    const float* Wek  = (const float*)d_in[10];
    const float* bek  = (const float*)d_in[11];
    const float* Wev  = (const float*)d_in[12];
    const float* bev  = (const float*)d_in[13];
    float* out = (float*)d_out;

    const int smemA = (16 * 257 + 64 * 260) * 4;     // 83008 B
    const int smemB = 11720 * 4;                     // 46880 B
    cudaFuncSetAttribute(node_proj_kernel, cudaFuncAttributeMaxDynamicSharedMemorySize, smemA);
    cudaFuncSetAttribute(attn_kernel, cudaFuncAttributeMaxDynamicSharedMemorySize, smemB);

    weight_frag_kernel<<<16, 256>>>(Weq, Wek);

    dim3 gridA(64, 3);
    node_proj_kernel<<<gridA, 256, smemA>>>(node, Wnq, bnq, Wnk, bnk, Wnv, bnv, beq, bek, bev);

    dim3 gridB(N_SZ, B_SZ);
    attn_kernel<<<gridB, 256, smemB>>>(edge);

    dim3 gridC1(32, HEADS, B_SZ);
    outp_kernel<<<gridC1, 256>>>();

    dim3 gridC2(8, HEADS, B_SZ);
    outr_kernel<<<gridC2, 256>>>(Wev, out);
}

// round 10
// speedup vs baseline: 1.1158x; 1.1158x over previous
#include <cuda_runtime.h>
#include <cuda_fp16.h>
#include <math.h>

#define B_SZ 2
#define N_SZ 512
#define EDIM 64
#define NDIM 256
#define HEADS 8
#define DH 32
#define SCALE_F 0.17677669529663687f  // 1/sqrt(32)

// ---------------- scratch (device globals; no allocation allowed) ----------------
__device__ float g_qc[B_SZ * N_SZ * NDIM];   // nq + beq
__device__ float g_kc[B_SZ * N_SZ * NDIM];   // nk + bek
__device__ float g_vc[B_SZ * N_SZ * NDIM];   // nv + bev
__device__ float g_att[B_SZ * HEADS * N_SZ * N_SZ];  // unnormalized softmax (16MB)
__device__ float g_ce[B_SZ * N_SZ * HEADS * EDIM];   // ctx_e per (b,i,h,64)
__device__ float g_ssum[B_SZ * N_SZ * HEADS];        // softmax denominators
__device__ uint2 g_wfq16[4096];  // fp16 fragment-ordered Weq [h][ni][ks][lane]
__device__ uint2 g_wfk16[4096];  // fp16 fragment-ordered Wek
__device__ float g_po[B_SZ * HEADS * 4 * N_SZ * DH]; // att@vc partials

// ---------------- helpers ----------------
__device__ __forceinline__ unsigned f2tf(float f) {
    unsigned u; asm("cvt.rna.tf32.f32 %0, %1;" : "=r"(u) : "f"(f)); return u;
}
__device__ __forceinline__ unsigned pack_h2(float x, float y) {
    __half2 h = __floats2half2_rn(x, y);
    return *(unsigned*)&h;
}
__device__ __forceinline__ void mma_tf32(float* d, const unsigned* a, const unsigned* b) {
    asm("mma.sync.aligned.m16n8k8.row.col.f32.tf32.tf32.f32 "
        "{%0,%1,%2,%3}, {%4,%5,%6,%7}, {%8,%9}, {%0,%1,%2,%3};"
        : "+f"(d[0]), "+f"(d[1]), "+f"(d[2]), "+f"(d[3])
        : "r"(a[0]), "r"(a[1]), "r"(a[2]), "r"(a[3]), "r"(b[0]), "r"(b[1]));
}
__device__ __forceinline__ void mma_f16(float* d, const unsigned* a, const unsigned* b) {
    asm("mma.sync.aligned.m16n8k16.row.col.f32.f16.f16.f32 "
        "{%0,%1,%2,%3}, {%4,%5,%6,%7}, {%8,%9}, {%0,%1,%2,%3};"
        : "+f"(d[0]), "+f"(d[1]), "+f"(d[2]), "+f"(d[3])
        : "r"(a[0]), "r"(a[1]), "r"(a[2]), "r"(a[3]), "r"(b[0]), "r"(b[1]));
}
__device__ __forceinline__ void cp_async16(void* smem_dst, const void* gsrc) {
    unsigned s = (unsigned)__cvta_generic_to_shared(smem_dst);
    asm volatile("cp.async.cg.shared.global [%0], [%1], 16;" :: "r"(s), "l"(gsrc));
}
__device__ __forceinline__ void ldsm_x4(unsigned* r, const __half* p) {
    unsigned addr = (unsigned)__cvta_generic_to_shared(p);
    asm volatile("ldmatrix.sync.aligned.m8n8.x4.shared.b16 {%0,%1,%2,%3}, [%4];"
        : "=r"(r[0]), "=r"(r[1]), "=r"(r[2]), "=r"(r[3]) : "r"(addr));
}

// =================================================================================
// Kernel W: build fp16 fragment-ordered weight tables.
// =================================================================================
__global__ __launch_bounds__(256) void weight_frag_kernel(
    const float* __restrict__ Weq, const float* __restrict__ Wek)
{
    int idx = blockIdx.x * 256 + threadIdx.x;   // 0..4095
    if (idx >= 4096) return;
    int l  = idx & 31;
    int ks = (idx >> 5) & 3;
    int ni = (idx >> 7) & 3;
    int hh = idx >> 9;
    int gg = l >> 2, cc = l & 3;
    int wrow = hh * 32 + ni * 8 + gg;
    const float* wq = Weq + wrow * 64 + ks * 16;
    const float* wk = Wek + wrow * 64 + ks * 16;
    g_wfq16[idx] = make_uint2(pack_h2(wq[2*cc], wq[2*cc+1]), pack_h2(wq[2*cc+8], wq[2*cc+9]));
    g_wfk16[idx] = make_uint2(pack_h2(wk[2*cc], wk[2*cc+1]), pack_h2(wk[2*cc+8], wk[2*cc+9]));
}

// =================================================================================
// Kernel A: node projections. grid (32, 3), 32 rows/CTA, warp-uniform col groups.
// =================================================================================
__global__ __launch_bounds__(256) void node_proj_kernel(
    const float* __restrict__ node,
    const float* __restrict__ Wnq, const float* __restrict__ bnq,
    const float* __restrict__ Wnk, const float* __restrict__ bnk,
    const float* __restrict__ Wnv, const float* __restrict__ bnv,
    const float* __restrict__ beq, const float* __restrict__ bek,
    const float* __restrict__ bev)
{
    extern __shared__ float smA[];
    float* node_s = smA;              // 32*257 = 8224
    float* wt     = smA + 32 * 257;   // 64*260 = 16640
    // total 24864 floats = 99456 B

    const int tid = threadIdx.x;
    const int r  = tid & 31;          // row (lane)
    const int cg = tid >> 5;          // warp = 32-col group (uniform per warp)
    const int r0 = blockIdx.x * 32;
    const int p  = blockIdx.y;

    const float* W  = (p == 0) ? Wnq : (p == 1) ? Wnk : Wnv;
    const float* b1 = (p == 0) ? bnq : (p == 1) ? bnk : bnv;
    const float* b2 = (p == 0) ? beq : (p == 1) ? bek : bev;
    float* dst = (p == 0) ? g_qc : (p == 1) ? g_kc : g_vc;

    for (int idx = tid; idx < 32 * 256; idx += 256) {
        int rr = idx >> 8, k = idx & 255;
        node_s[rr * 257 + k] = node[(r0 + rr) * 256 + k];
    }

    float acc[32];
    #pragma unroll
    for (int q = 0; q < 32; q++) acc[q] = 0.f;

    for (int kt = 0; kt < 4; kt++) {
        __syncthreads();
        for (int idx = tid; idx < 64 * 256; idx += 256) {
            int c = idx >> 6, kk = idx & 63;
            wt[kk * 260 + c] = W[c * 256 + kt * 64 + kk];
        }
        __syncthreads();
        #pragma unroll 2
        for (int kk = 0; kk < 64; kk++) {
            float nv = node_s[r * 257 + kt * 64 + kk];
            const float* wrow = &wt[kk * 260 + cg * 32];
            #pragma unroll
            for (int q4 = 0; q4 < 8; q4++) {
                float4 w = *(const float4*)(wrow + q4 * 4);
                acc[q4*4+0] += w.x * nv;
                acc[q4*4+1] += w.y * nv;
                acc[q4*4+2] += w.z * nv;
                acc[q4*4+3] += w.w * nv;
            }
        }
    }
    int row = r0 + r;
    #pragma unroll
    for (int q4 = 0; q4 < 8; q4++) {
        float4 bb1 = *(const float4*)&b1[cg * 32 + q4 * 4];
        float4 bb2 = *(const float4*)&b2[cg * 32 + q4 * 4];
        float4 v;
        v.x = acc[q4 * 4 + 0] + bb1.x + bb2.x;
        v.y = acc[q4 * 4 + 1] + bb1.y + bb2.y;
        v.z = acc[q4 * 4 + 2] + bb1.z + bb2.z;
        v.w = acc[q4 * 4 + 3] + bb1.w + bb2.w;
        *(float4*)&dst[row * 256 + cg * 32 + q4 * 4] = v;
    }
}

// =================================================================================
// Kernel B: per (b,i) CTA, 256 threads = 8 warps (warp = head), 2 CTAs/SM.
// Phase 1: fp16 smem tiles (144B stride, LDSM-conflict-free) + ldmatrix A-frags;
// staged via LDG->cvt->STS with register double-buffer. fp16 mma for qk.
// Phase 2 (separate, R8-style): tf32 mma ctx_e on fp32 cp.async-staged tiles.
// =================================================================================
__global__ __launch_bounds__(256, 2) void attn_kernel(
    const float* __restrict__ edge)
{
    extern __shared__ float sm[];
    float* sQK = sm;              // 8 x 516 = 4128
    float* sQC = sm + 4128;       // 256
    float* sCE = sm + 4384;       // 512
    float* sE  = sm + 4896;       // union: phase1 fp16 ring 3x(32x72h)=3456 fl;
                                  //        phase2 fp32 256x68 = 17408 fl
    // total 22304 floats = 89216 bytes

    const int i = blockIdx.x;
    const int b = blockIdx.y;
    const int tid = threadIdx.x;
    const int lane = tid & 31;
    const int h = tid >> 5;      // warp = head
    const int g = lane >> 2;
    const int c = lane & 3;

    const int bN = b * N_SZ;
    const float* edgeRowBase = edge + (size_t)(bN + i) * N_SZ * EDIM;
    __half* sE16 = (__half*)sE;

    sQC[tid] = g_qc[(bN + i) * NDIM + tid];

    // per-thread staging mapping: row = tid>>3 (32 rows), q = tid&7 (8 halves)
    const int strow = tid >> 3, stq = tid & 7;
    const float4* esrc0 = (const float4*)(edgeRowBase) + tid * 2;

    // ldmatrix per-lane base: lanes 0-15 -> row lane, col 0; 16-31 -> row lane-16, col 8
    const int lrow = lane & 15;
    const int lcol = (lane >> 4) << 3;

    // ---- prologue: tile 0 staged, tile 1 in regs ----
    float4 ra, rb;
    ra = __ldg(esrc0);
    rb = __ldg(esrc0 + 1);
    {
        uint4 v;
        v.x = pack_h2(ra.x, ra.y); v.y = pack_h2(ra.z, ra.w);
        v.z = pack_h2(rb.x, rb.y); v.w = pack_h2(rb.z, rb.w);
        *(uint4*)(sE16 + strow * 72 + stq * 8) = v;
    }
    ra = __ldg(esrc0 + 256);      // tile 1 (32*64/4 = 512 float4 per tile; +512? no:
    rb = __ldg(esrc0 + 256 + 1);  //  tile stride = 32*64 floats = 512 float4)
    // fix: tile stride in float4 = 512
    ra = __ldg(esrc0 + 512);
    rb = __ldg(esrc0 + 512 + 1);
    __syncthreads();   // tile 0 visible

    // ---------------- Phase 1: 16 tiles of 32 j, fp16 mma + ldmatrix ----------------
    for (int jt = 0; jt < 16; jt++) {
        // store next tile (in regs) and start fetch of tile jt+2
        if (jt < 15) {
            __half* buf = sE16 + ((jt + 1) % 3) * 2304;
            uint4 v;
            v.x = pack_h2(ra.x, ra.y); v.y = pack_h2(ra.z, ra.w);
            v.z = pack_h2(rb.x, rb.y); v.w = pack_h2(rb.z, rb.w);
            *(uint4*)(buf + strow * 72 + stq * 8) = v;
        }
        if (jt < 14) {
            ra = __ldg(esrc0 + (size_t)(jt + 2) * 512);
            rb = __ldg(esrc0 + (size_t)(jt + 2) * 512 + 1);
        }

        const __half* eb = sE16 + (jt % 3) * 2304 + lrow * 72 + lcol;
        const int jg0 = jt * 32;

        float Dq[2][4][4], Dk[2][4][4];
        #pragma unroll
        for (int mi = 0; mi < 2; mi++)
            #pragma unroll
            for (int ni = 0; ni < 4; ni++)
                #pragma unroll
                for (int e = 0; e < 4; e++) { Dq[mi][ni][e] = 0.f; Dk[mi][ni][e] = 0.f; }

        #pragma unroll
        for (int ks = 0; ks < 4; ks++) {
            unsigned a0[4], a1[4];
            ldsm_x4(a0, eb + ks * 16);
            ldsm_x4(a1, eb + 16 * 72 + ks * 16);
            #pragma unroll
            for (int ni = 0; ni < 4; ni++) {
                const int wi = ((h * 4 + ni) * 4 + ks) * 32 + lane;
                uint2 bq = __ldg(&g_wfq16[wi]);
                uint2 bk = __ldg(&g_wfk16[wi]);
                mma_f16(Dq[0][ni], a0, (const unsigned*)&bq);
                mma_f16(Dq[1][ni], a1, (const unsigned*)&bq);
                mma_f16(Dk[0][ni], a0, (const unsigned*)&bk);
                mma_f16(Dk[1][ni], a1, (const unsigned*)&bk);
            }
        }

        // combine: qk[j] = sum_d (EQ+qc)(EK+kc)
        float acc[4] = {0.f, 0.f, 0.f, 0.f};
        #pragma unroll
        for (int mi = 0; mi < 2; mi++) {
            int r0 = mi * 16 + g;
            #pragma unroll
            for (int ni = 0; ni < 4; ni++) {
                int ch = h * 32 + ni * 8 + 2 * c;
                float q0 = sQC[ch], q1 = sQC[ch + 1];
                float2 kA = __ldg((const float2*)(g_kc + (size_t)(bN + jg0 + r0) * NDIM + ch));
                float2 kB = __ldg((const float2*)(g_kc + (size_t)(bN + jg0 + r0 + 8) * NDIM + ch));
                acc[mi * 2]     += (Dq[mi][ni][0] + q0) * (Dk[mi][ni][0] + kA.x)
                                 + (Dq[mi][ni][1] + q1) * (Dk[mi][ni][1] + kA.y);
                acc[mi * 2 + 1] += (Dq[mi][ni][2] + q0) * (Dk[mi][ni][2] + kB.x)
                                 + (Dq[mi][ni][3] + q1) * (Dk[mi][ni][3] + kB.y);
            }
        }
        #pragma unroll
        for (int t = 1; t <= 2; t <<= 1) {
            acc[0] += __shfl_xor_sync(0xffffffffu, acc[0], t);
            acc[1] += __shfl_xor_sync(0xffffffffu, acc[1], t);
            acc[2] += __shfl_xor_sync(0xffffffffu, acc[2], t);
            acc[3] += __shfl_xor_sync(0xffffffffu, acc[3], t);
        }
        if (c == 0) {
            sQK[h * 516 + jg0 + g]      = acc[0] * SCALE_F;
            sQK[h * 516 + jg0 + g + 8]  = acc[1] * SCALE_F;
            sQK[h * 516 + jg0 + 16 + g] = acc[2] * SCALE_F;
            sQK[h * 516 + jg0 + 24 + g] = acc[3] * SCALE_F;
        }
        __syncthreads();   // tile jt readers done; tile jt+1 STS visible
    }

    // ---------------- Softmax: one warp owns head h's full row ----------------
    float* srow = sQK + h * 516;
    {
        float m = -1e30f;
        for (int jj = lane; jj < 512; jj += 32) m = fmaxf(m, srow[jj]);
        #pragma unroll
        for (int off = 16; off > 0; off >>= 1) m = fmaxf(m, __shfl_xor_sync(0xffffffffu, m, off));
        float ssum = 0.f;
        float* gatt = g_att + ((size_t)(b * HEADS + h) * N_SZ + i) * N_SZ;
        for (int jj = lane; jj < 512; jj += 32) {
            float p = __expf(srow[jj] - m);
            float pr = __uint_as_float(f2tf(p));  // tf32-representable: exact in mma
            srow[jj] = pr;
            gatt[jj] = pr;
            ssum += pr;
        }
        #pragma unroll
        for (int off = 16; off > 0; off >>= 1) ssum += __shfl_xor_sync(0xffffffffu, ssum, off);
        if (lane == 0) g_ssum[(size_t)(bN + i) * HEADS + h] = ssum;
    }

    // ---------------- Phase 2: ctx_e = att @ E via tf32 mma ----------------------
    const int nt = h;            // warp = 8-col d-slice
    float Dc[4] = {0.f, 0.f, 0.f, 0.f};

    for (int pass = 0; pass < 2; pass++) {
        __syncthreads();
        {
            const float4* src = (const float4*)(edgeRowBase + (size_t)pass * 256 * EDIM);
            #pragma unroll
            for (int u = 0; u < 16; u++) {
                int idx = tid + u * 256;
                int row = idx >> 4, q = idx & 15;
                cp_async16(sE + row * 68 + q * 4, src + idx);
            }
            asm volatile("cp.async.commit_group;");
            asm volatile("cp.async.wait_group 0;");
        }
        __syncthreads();

        #pragma unroll
        for (int cc = 0; cc < 32; cc++) {
            const int jl = cc * 8;
            const int jg = pass * 256 + jl;
            unsigned aa[4], bb[2];
            aa[0] = __float_as_uint(sQK[g * 516 + jg + c]);
            aa[1] = 0u;
            aa[2] = __float_as_uint(sQK[g * 516 + jg + c + 4]);
            aa[3] = 0u;
            bb[0] = __float_as_uint(sE[(jl + c) * 68 + nt * 8 + g]);
            bb[1] = __float_as_uint(sE[(jl + c + 4) * 68 + nt * 8 + g]);
            mma_tf32(Dc, aa, bb);
        }
    }
    sCE[g * 64 + nt * 8 + 2 * c]     = Dc[0];
    sCE[g * 64 + nt * 8 + 2 * c + 1] = Dc[1];
    __syncthreads();
    g_ce[(size_t)(bN + i) * 512 + tid]       = sCE[tid];
    g_ce[(size_t)(bN + i) * 512 + 256 + tid] = sCE[256 + tid];
}

// =================================================================================
// Kernel C1: att@vc partials. grid (32, 8, 2), 256 threads, 16KB smem.
// =================================================================================
__global__ __launch_bounds__(256) void outp_kernel()
{
    __shared__ float svc[128 * 32];

    const int x  = blockIdx.x;
    const int jq = x >> 3;
    const int it = x & 7;
    const int h  = blockIdx.y;
    const int b  = blockIdx.z;
    const int tid = threadIdx.x;
    const int ti = tid >> 5;
    const int lane = tid & 31;
    const int j0 = jq * 128;

    for (int idx = tid; idx < 128 * 8; idx += 256) {
        int j = idx >> 3, q = idx & 7;
        float4 v = __ldg((const float4*)&g_vc[(size_t)(b * N_SZ + j0 + j) * NDIM + h * 32 + q * 4]);
        *(float4*)&svc[j * 32 + q * 4] = v;
    }
    __syncthreads();

    #pragma unroll
    for (int half = 0; half < 2; half++) {
        const int i0 = it * 64 + ti * 8 + half * 4;
        const float* arow = g_att + ((size_t)(b * HEADS + h) * N_SZ + i0) * N_SZ + j0;
        float acc0 = 0.f, acc1 = 0.f, acc2 = 0.f, acc3 = 0.f;
        #pragma unroll 4
        for (int j = 0; j < 128; j += 4) {
            float4 a0 = __ldg((const float4*)(arow + j));
            float4 a1 = __ldg((const float4*)(arow + 512 + j));
            float4 a2 = __ldg((const float4*)(arow + 1024 + j));
            float4 a3 = __ldg((const float4*)(arow + 1536 + j));
            float v0 = svc[(j + 0) * 32 + lane];
            float v1 = svc[(j + 1) * 32 + lane];
            float v2 = svc[(j + 2) * 32 + lane];
            float v3 = svc[(j + 3) * 32 + lane];
            acc0 += a0.x * v0 + a0.y * v1 + a0.z * v2 + a0.w * v3;
            acc1 += a1.x * v0 + a1.y * v1 + a1.z * v2 + a1.w * v3;
            acc2 += a2.x * v0 + a2.y * v1 + a2.z * v2 + a2.w * v3;
            acc3 += a3.x * v0 + a3.y * v1 + a3.z * v2 + a3.w * v3;
        }
        float* po = g_po + (((size_t)(b * HEADS + h) * 4 + jq) * N_SZ + i0) * DH + lane;
        po[0 * DH] = acc0;
        po[1 * DH] = acc1;
        po[2 * DH] = acc2;
        po[3 * DH] = acc3;
    }
}

// =================================================================================
// Kernel C2: reduce partials + Wev·ctx_e epilogue. grid (8, 8, 2), 256 threads.
// =================================================================================
__global__ __launch_bounds__(256) void outr_kernel(
    const float* __restrict__ Wev,
    float* __restrict__ out)
{
    __shared__ float sWev[32 * 65];
    __shared__ float sCe[64 * 64];

    const int it = blockIdx.x;
    const int h  = blockIdx.y;
    const int b  = blockIdx.z;
    const int tid = threadIdx.x;
    const int ti = tid >> 5;
    const int lane = tid & 31;

    for (int idx = tid; idx < 2048; idx += 256) {
        int row = idx >> 6, dp = idx & 63;
        sWev[row * 65 + dp] = __ldg(&Wev[(h * 32 + row) * 64 + dp]);
    }
    for (int idx = tid; idx < 64 * 16; idx += 256) {
        int il = idx >> 4, q = idx & 15;
        float4 v = __ldg((const float4*)&g_ce[(size_t)(b * N_SZ + it * 64 + il) * 512 + h * 64 + q * 4]);
        *(float4*)&sCe[il * 64 + q * 4] = v;
    }
    __syncthreads();

    #pragma unroll
    for (int ii = 0; ii < 8; ii++) {
        int il = ti * 8 + ii;
        int ig = it * 64 + il;
        float a = 0.f;
        #pragma unroll
        for (int jq = 0; jq < 4; jq++)
            a += __ldg(&g_po[(((size_t)(b * HEADS + h) * 4 + jq) * N_SZ + ig) * DH + lane]);
        float dot = 0.f;
        #pragma unroll 8
        for (int dp = 0; dp < 64; dp++)
            dot += sCe[il * 64 + dp] * sWev[lane * 65 + dp];
        float inv = 1.f / __ldg(&g_ssum[(size_t)(b * N_SZ + ig) * HEADS + h]);
        out[(size_t)(b * N_SZ + ig) * NDIM + h * 32 + lane] = (dot + a) * inv;
    }
}

// =================================================================================
extern "C" void kernel_launch(void* const* d_in, const int* in_sizes, int n_in,
                              void* d_out, int out_size)
{
    const float* node = (const float*)d_in[0];
    const float* edge = (const float*)d_in[1];
    const float* Wnq  = (const float*)d_in[2];
    const float* bnq  = (const float*)d_in[3];
    const float* Wnk  = (const float*)d_in[4];
    const float* bnk  = (const float*)d_in[5];
    const float* Wnv  = (const float*)d_in[6];
    const float* bnv  = (const float*)d_in[7];
    const float* Weq  = (const float*)d_in[8];
    const float* beq  = (const float*)d_in[9];
    const float* Wek  = (const float*)d_in[10];
    const float* bek  = (const float*)d_in[11];
    const float* Wev  = (const float*)d_in[12];
    const float* bev  = (const float*)d_in[13];
    float* out = (float*)d_out;

    const int smemA = (32 * 257 + 64 * 260) * 4;     // 99456 B
    const int smemB = 22304 * 4;                     // 89216 B
    cudaFuncSetAttribute(node_proj_kernel, cudaFuncAttributeMaxDynamicSharedMemorySize, smemA);
    cudaFuncSetAttribute(attn_kernel, cudaFuncAttributeMaxDynamicSharedMemorySize, smemB);

    weight_frag_kernel<<<16, 256>>>(Weq, Wek);

    dim3 gridA(32, 3);
    node_proj_kernel<<<gridA, 256, smemA>>>(node, Wnq, bnq, Wnk, bnk, Wnv, bnv, beq, bek, bev);

    dim3 gridB(N_SZ, B_SZ);
    attn_kernel<<<gridB, 256, smemB>>>(edge);

    dim3 gridC1(32, HEADS, B_SZ);
    outp_kernel<<<gridC1, 256>>>();

    dim3 gridC2(8, HEADS, B_SZ);
    outr_kernel<<<gridC2, 256>>>(Wev, out);
}

// round 11
// speedup vs baseline: 1.2277x; 1.1003x over previous
#include <cuda_runtime.h>
#include <cuda_fp16.h>
#include <math.h>

#define B_SZ 2
#define N_SZ 512
#define EDIM 64
#define NDIM 256
#define HEADS 8
#define DH 32
#define SCALE_F 0.17677669529663687f  // 1/sqrt(32)

// ---------------- scratch (device globals; no allocation allowed) ----------------
__device__ float g_qc[B_SZ * N_SZ * NDIM];   // nq + beq
__device__ float g_kc[B_SZ * N_SZ * NDIM];   // nk + bek
__device__ float g_vc[B_SZ * N_SZ * NDIM];   // nv + bev
__device__ float g_att[B_SZ * HEADS * N_SZ * N_SZ];  // unnormalized softmax (16MB)
__device__ float g_ce[B_SZ * N_SZ * HEADS * EDIM];   // ctx_e per (b,i,h,64)
__device__ float g_ssum[B_SZ * N_SZ * HEADS];        // softmax denominators
__device__ uint2 g_wfq16[4096];  // fp16 fragment-ordered Weq [h][ni][ks][lane]
__device__ uint2 g_wfk16[4096];  // fp16 fragment-ordered Wek
__device__ float g_po[B_SZ * HEADS * 4 * N_SZ * DH]; // att@vc partials

// ---------------- helpers ----------------
__device__ __forceinline__ unsigned f2tf(float f) {
    unsigned u; asm("cvt.rna.tf32.f32 %0, %1;" : "=r"(u) : "f"(f)); return u;
}
__device__ __forceinline__ unsigned pack_h2(float x, float y) {
    __half2 h = __floats2half2_rn(x, y);
    return *(unsigned*)&h;
}
__device__ __forceinline__ void mma_tf32(float* d, const unsigned* a, const unsigned* b) {
    asm("mma.sync.aligned.m16n8k8.row.col.f32.tf32.tf32.f32 "
        "{%0,%1,%2,%3}, {%4,%5,%6,%7}, {%8,%9}, {%0,%1,%2,%3};"
        : "+f"(d[0]), "+f"(d[1]), "+f"(d[2]), "+f"(d[3])
        : "r"(a[0]), "r"(a[1]), "r"(a[2]), "r"(a[3]), "r"(b[0]), "r"(b[1]));
}
__device__ __forceinline__ void mma_f16(float* d, const unsigned* a, const unsigned* b) {
    asm("mma.sync.aligned.m16n8k16.row.col.f32.f16.f16.f32 "
        "{%0,%1,%2,%3}, {%4,%5,%6,%7}, {%8,%9}, {%0,%1,%2,%3};"
        : "+f"(d[0]), "+f"(d[1]), "+f"(d[2]), "+f"(d[3])
        : "r"(a[0]), "r"(a[1]), "r"(a[2]), "r"(a[3]), "r"(b[0]), "r"(b[1]));
}
__device__ __forceinline__ void cp_async16(void* smem_dst, const void* gsrc) {
    unsigned s = (unsigned)__cvta_generic_to_shared(smem_dst);
    asm volatile("cp.async.cg.shared.global [%0], [%1], 16;" :: "r"(s), "l"(gsrc));
}
__device__ __forceinline__ void ldsm_x4(unsigned* r, const __half* p) {
    unsigned addr = (unsigned)__cvta_generic_to_shared(p);
    asm volatile("ldmatrix.sync.aligned.m8n8.x4.shared.b16 {%0,%1,%2,%3}, [%4];"
        : "=r"(r[0]), "=r"(r[1]), "=r"(r[2]), "=r"(r[3]) : "r"(addr));
}

// =================================================================================
// Kernel W: build fp16 fragment-ordered weight tables.
// =================================================================================
__global__ __launch_bounds__(256) void weight_frag_kernel(
    const float* __restrict__ Weq, const float* __restrict__ Wek)
{
    int idx = blockIdx.x * 256 + threadIdx.x;   // 0..4095
    if (idx >= 4096) return;
    int l  = idx & 31;
    int ks = (idx >> 5) & 3;
    int ni = (idx >> 7) & 3;
    int hh = idx >> 9;
    int gg = l >> 2, cc = l & 3;
    int wrow = hh * 32 + ni * 8 + gg;
    const float* wq = Weq + wrow * 64 + ks * 16;
    const float* wk = Wek + wrow * 64 + ks * 16;
    g_wfq16[idx] = make_uint2(pack_h2(wq[2*cc], wq[2*cc+1]), pack_h2(wq[2*cc+8], wq[2*cc+9]));
    g_wfk16[idx] = make_uint2(pack_h2(wk[2*cc], wk[2*cc+1]), pack_h2(wk[2*cc+8], wk[2*cc+9]));
}

// =================================================================================
// Kernel A: node projections. grid (32, 3), 32 rows/CTA, warp-uniform col groups.
// =================================================================================
__global__ __launch_bounds__(256) void node_proj_kernel(
    const float* __restrict__ node,
    const float* __restrict__ Wnq, const float* __restrict__ bnq,
    const float* __restrict__ Wnk, const float* __restrict__ bnk,
    const float* __restrict__ Wnv, const float* __restrict__ bnv,
    const float* __restrict__ beq, const float* __restrict__ bek,
    const float* __restrict__ bev)
{
    extern __shared__ float smA[];
    float* node_s = smA;              // 32*257 = 8224
    float* wt     = smA + 32 * 257;   // 64*260 = 16640

    const int tid = threadIdx.x;
    const int r  = tid & 31;
    const int cg = tid >> 5;
    const int r0 = blockIdx.x * 32;
    const int p  = blockIdx.y;

    const float* W  = (p == 0) ? Wnq : (p == 1) ? Wnk : Wnv;
    const float* b1 = (p == 0) ? bnq : (p == 1) ? bnk : bnv;
    const float* b2 = (p == 0) ? beq : (p == 1) ? bek : bev;
    float* dst = (p == 0) ? g_qc : (p == 1) ? g_kc : g_vc;

    for (int idx = tid; idx < 32 * 256; idx += 256) {
        int rr = idx >> 8, k = idx & 255;
        node_s[rr * 257 + k] = node[(r0 + rr) * 256 + k];
    }

    float acc[32];
    #pragma unroll
    for (int q = 0; q < 32; q++) acc[q] = 0.f;

    for (int kt = 0; kt < 4; kt++) {
        __syncthreads();
        for (int idx = tid; idx < 64 * 256; idx += 256) {
            int c = idx >> 6, kk = idx & 63;
            wt[kk * 260 + c] = W[c * 256 + kt * 64 + kk];
        }
        __syncthreads();
        #pragma unroll 2
        for (int kk = 0; kk < 64; kk++) {
            float nv = node_s[r * 257 + kt * 64 + kk];
            const float* wrow = &wt[kk * 260 + cg * 32];
            #pragma unroll
            for (int q4 = 0; q4 < 8; q4++) {
                float4 w = *(const float4*)(wrow + q4 * 4);
                acc[q4*4+0] += w.x * nv;
                acc[q4*4+1] += w.y * nv;
                acc[q4*4+2] += w.z * nv;
                acc[q4*4+3] += w.w * nv;
            }
        }
    }
    int row = r0 + r;
    #pragma unroll
    for (int q4 = 0; q4 < 8; q4++) {
        float4 bb1 = *(const float4*)&b1[cg * 32 + q4 * 4];
        float4 bb2 = *(const float4*)&b2[cg * 32 + q4 * 4];
        float4 v;
        v.x = acc[q4 * 4 + 0] + bb1.x + bb2.x;
        v.y = acc[q4 * 4 + 1] + bb1.y + bb2.y;
        v.z = acc[q4 * 4 + 2] + bb1.z + bb2.z;
        v.w = acc[q4 * 4 + 3] + bb1.w + bb2.w;
        *(float4*)&dst[row * 256 + cg * 32 + q4 * 4] = v;
    }
}

// =================================================================================
// Kernel B: per (b,i) CTA, 256 threads = 8 warps (warp = head), 2 CTAs/SM.
// Phase 1: ldmatrix A-frags; weights + qc RESIDENT IN REGISTERS (m-split halves
// accumulator pressure). Phase 2: tf32 mma ctx_e (R8-style bulk).
// =================================================================================
__global__ __launch_bounds__(256, 2) void attn_kernel(
    const float* __restrict__ edge)
{
    extern __shared__ float sm[];
    float* sQK = sm;              // 8 x 516 = 4128
    float* sCE = sm + 4128;       // 512
    float* sE  = sm + 4640;       // union: phase1 fp16 ring 3x(32x72h)=3456 fl;
                                  //        phase2 fp32 256x68 = 17408 fl
    // total 22048 floats = 88192 bytes

    const int i = blockIdx.x;
    const int b = blockIdx.y;
    const int tid = threadIdx.x;
    const int lane = tid & 31;
    const int h = tid >> 5;      // warp = head
    const int g = lane >> 2;
    const int c = lane & 3;

    const int bN = b * N_SZ;
    const float* edgeRowBase = edge + (size_t)(bN + i) * N_SZ * EDIM;
    __half* sE16 = (__half*)sE;

    // ---- hoist weight fragments + qc into registers (reused by all 16 tiles) ----
    uint2 wq[4][4], wk[4][4];
    float2 qcr[4];
    #pragma unroll
    for (int ni = 0; ni < 4; ni++) {
        #pragma unroll
        for (int ks = 0; ks < 4; ks++) {
            const int wi = ((h * 4 + ni) * 4 + ks) * 32 + lane;
            wq[ni][ks] = __ldg(&g_wfq16[wi]);
            wk[ni][ks] = __ldg(&g_wfk16[wi]);
        }
        qcr[ni] = __ldg((const float2*)&g_qc[(size_t)(bN + i) * NDIM + h * 32 + ni * 8 + 2 * c]);
    }

    // per-thread staging mapping: row = tid>>3 (32 rows), q = tid&7 (8 half-octets)
    const int strow = tid >> 3, stq = tid & 7;
    const float4* esrc0 = (const float4*)(edgeRowBase) + tid * 2;

    // ldmatrix per-lane base
    const int lrow = lane & 15;
    const int lcol = (lane >> 4) << 3;

    // ---- prologue: tile 0 staged, tile 1 in regs ----
    float4 ra, rb;
    ra = __ldg(esrc0);
    rb = __ldg(esrc0 + 1);
    {
        uint4 v;
        v.x = pack_h2(ra.x, ra.y); v.y = pack_h2(ra.z, ra.w);
        v.z = pack_h2(rb.x, rb.y); v.w = pack_h2(rb.z, rb.w);
        *(uint4*)(sE16 + strow * 72 + stq * 8) = v;
    }
    ra = __ldg(esrc0 + 512);      // tile stride = 32*64 floats = 512 float4
    rb = __ldg(esrc0 + 513);
    __syncthreads();   // tile 0 visible

    // ---------------- Phase 1: 16 tiles of 32 j, fp16 mma + ldmatrix ----------------
    for (int jt = 0; jt < 16; jt++) {
        if (jt < 15) {
            __half* buf = sE16 + ((jt + 1) % 3) * 2304;
            uint4 v;
            v.x = pack_h2(ra.x, ra.y); v.y = pack_h2(ra.z, ra.w);
            v.z = pack_h2(rb.x, rb.y); v.w = pack_h2(rb.z, rb.w);
            *(uint4*)(buf + strow * 72 + stq * 8) = v;
        }
        if (jt < 14) {
            ra = __ldg(esrc0 + (size_t)(jt + 2) * 512);
            rb = __ldg(esrc0 + (size_t)(jt + 2) * 512 + 1);
        }

        const __half* eb = sE16 + (jt % 3) * 2304;
        const int jg0 = jt * 32;

        // m-split: process the two 16-row halves sequentially (32 live acc regs)
        #pragma unroll
        for (int mi = 0; mi < 2; mi++) {
            float Dq[4][4], Dk[4][4];
            #pragma unroll
            for (int ni = 0; ni < 4; ni++)
                #pragma unroll
                for (int e = 0; e < 4; e++) { Dq[ni][e] = 0.f; Dk[ni][e] = 0.f; }

            const __half* ebm = eb + (mi * 16 + lrow) * 72 + lcol;
            #pragma unroll
            for (int ks = 0; ks < 4; ks++) {
                unsigned a[4];
                ldsm_x4(a, ebm + ks * 16);
                #pragma unroll
                for (int ni = 0; ni < 4; ni++) {
                    mma_f16(Dq[ni], a, (const unsigned*)&wq[ni][ks]);
                    mma_f16(Dk[ni], a, (const unsigned*)&wk[ni][ks]);
                }
            }

            // combine: qk[j] = sum_d (EQ+qc)(EK+kc) for rows jg0+mi*16+{g, g+8}
            const int r0 = mi * 16 + g;
            float accA = 0.f, accB = 0.f;
            #pragma unroll
            for (int ni = 0; ni < 4; ni++) {
                int ch = h * 32 + ni * 8 + 2 * c;
                float q0 = qcr[ni].x, q1 = qcr[ni].y;
                float2 kA = __ldg((const float2*)(g_kc + (size_t)(bN + jg0 + r0) * NDIM + ch));
                float2 kB = __ldg((const float2*)(g_kc + (size_t)(bN + jg0 + r0 + 8) * NDIM + ch));
                accA += (Dq[ni][0] + q0) * (Dk[ni][0] + kA.x)
                      + (Dq[ni][1] + q1) * (Dk[ni][1] + kA.y);
                accB += (Dq[ni][2] + q0) * (Dk[ni][2] + kB.x)
                      + (Dq[ni][3] + q1) * (Dk[ni][3] + kB.y);
            }
            #pragma unroll
            for (int t = 1; t <= 2; t <<= 1) {
                accA += __shfl_xor_sync(0xffffffffu, accA, t);
                accB += __shfl_xor_sync(0xffffffffu, accB, t);
            }
            if (c == 0) {
                sQK[h * 516 + jg0 + r0]     = accA * SCALE_F;
                sQK[h * 516 + jg0 + r0 + 8] = accB * SCALE_F;
            }
        }
        __syncthreads();   // tile jt readers done; tile jt+1 STS visible
    }

    // ---------------- Softmax: one warp owns head h's full row ----------------
    float* srow = sQK + h * 516;
    {
        float m = -1e30f;
        for (int jj = lane; jj < 512; jj += 32) m = fmaxf(m, srow[jj]);
        #pragma unroll
        for (int off = 16; off > 0; off >>= 1) m = fmaxf(m, __shfl_xor_sync(0xffffffffu, m, off));
        float ssum = 0.f;
        float* gatt = g_att + ((size_t)(b * HEADS + h) * N_SZ + i) * N_SZ;
        for (int jj = lane; jj < 512; jj += 32) {
            float p = __expf(srow[jj] - m);
            float pr = __uint_as_float(f2tf(p));  // tf32-representable: exact in mma
            srow[jj] = pr;
            gatt[jj] = pr;
            ssum += pr;
        }
        #pragma unroll
        for (int off = 16; off > 0; off >>= 1) ssum += __shfl_xor_sync(0xffffffffu, ssum, off);
        if (lane == 0) g_ssum[(size_t)(bN + i) * HEADS + h] = ssum;
    }

    // ---------------- Phase 2: ctx_e = att @ E via tf32 mma ----------------------
    const int nt = h;            // warp = 8-col d-slice
    float Dc[4] = {0.f, 0.f, 0.f, 0.f};

    for (int pass = 0; pass < 2; pass++) {
        __syncthreads();
        {
            const float4* src = (const float4*)(edgeRowBase + (size_t)pass * 256 * EDIM);
            #pragma unroll
            for (int u = 0; u < 16; u++) {
                int idx = tid + u * 256;
                int row = idx >> 4, q = idx & 15;
                cp_async16(sE + row * 68 + q * 4, src + idx);
            }
            asm volatile("cp.async.commit_group;");
            asm volatile("cp.async.wait_group 0;");
        }
        __syncthreads();

        #pragma unroll
        for (int cc = 0; cc < 32; cc++) {
            const int jl = cc * 8;
            const int jg = pass * 256 + jl;
            unsigned aa[4], bb[2];
            aa[0] = __float_as_uint(sQK[g * 516 + jg + c]);
            aa[1] = 0u;
            aa[2] = __float_as_uint(sQK[g * 516 + jg + c + 4]);
            aa[3] = 0u;
            bb[0] = __float_as_uint(sE[(jl + c) * 68 + nt * 8 + g]);
            bb[1] = __float_as_uint(sE[(jl + c + 4) * 68 + nt * 8 + g]);
            mma_tf32(Dc, aa, bb);
        }
    }
    sCE[g * 64 + nt * 8 + 2 * c]     = Dc[0];
    sCE[g * 64 + nt * 8 + 2 * c + 1] = Dc[1];
    __syncthreads();
    g_ce[(size_t)(bN + i) * 512 + tid]       = sCE[tid];
    g_ce[(size_t)(bN + i) * 512 + 256 + tid] = sCE[256 + tid];
}

// =================================================================================
// Kernel C1: att@vc partials. grid (32, 8, 2), 256 threads, 16KB smem.
// 8 independent i-row streams per warp (MLP=8) to hide broadcast-load latency.
// =================================================================================
__global__ __launch_bounds__(256) void outp_kernel()
{
    __shared__ float svc[128 * 32];

    const int x  = blockIdx.x;
    const int jq = x >> 3;
    const int it = x & 7;
    const int h  = blockIdx.y;
    const int b  = blockIdx.z;
    const int tid = threadIdx.x;
    const int ti = tid >> 5;
    const int lane = tid & 31;
    const int j0 = jq * 128;

    for (int idx = tid; idx < 128 * 8; idx += 256) {
        int j = idx >> 3, q = idx & 7;
        float4 v = __ldg((const float4*)&g_vc[(size_t)(b * N_SZ + j0 + j) * NDIM + h * 32 + q * 4]);
        *(float4*)&svc[j * 32 + q * 4] = v;
    }
    __syncthreads();

    const int i0 = it * 64 + ti * 8;
    const float* arow = g_att + ((size_t)(b * HEADS + h) * N_SZ + i0) * N_SZ + j0;
    float acc[8];
    #pragma unroll
    for (int r = 0; r < 8; r++) acc[r] = 0.f;

    #pragma unroll 2
    for (int j = 0; j < 128; j += 4) {
        float4 a[8];
        #pragma unroll
        for (int r = 0; r < 8; r++)
            a[r] = __ldg((const float4*)(arow + (size_t)r * 512 + j));
        float v0 = svc[(j + 0) * 32 + lane];
        float v1 = svc[(j + 1) * 32 + lane];
        float v2 = svc[(j + 2) * 32 + lane];
        float v3 = svc[(j + 3) * 32 + lane];
        #pragma unroll
        for (int r = 0; r < 8; r++)
            acc[r] += a[r].x * v0 + a[r].y * v1 + a[r].z * v2 + a[r].w * v3;
    }
    float* po = g_po + (((size_t)(b * HEADS + h) * 4 + jq) * N_SZ + i0) * DH + lane;
    #pragma unroll
    for (int r = 0; r < 8; r++)
        po[(size_t)r * DH] = acc[r];
}

// =================================================================================
// Kernel C2: reduce partials + Wev·ctx_e epilogue. grid (8, 8, 2), 256 threads.
// =================================================================================
__global__ __launch_bounds__(256) void outr_kernel(
    const float* __restrict__ Wev,
    float* __restrict__ out)
{
    __shared__ float sWev[32 * 65];
    __shared__ float sCe[64 * 64];

    const int it = blockIdx.x;
    const int h  = blockIdx.y;
    const int b  = blockIdx.z;
    const int tid = threadIdx.x;
    const int ti = tid >> 5;
    const int lane = tid & 31;

    for (int idx = tid; idx < 2048; idx += 256) {
        int row = idx >> 6, dp = idx & 63;
        sWev[row * 65 + dp] = __ldg(&Wev[(h * 32 + row) * 64 + dp]);
    }
    for (int idx = tid; idx < 64 * 16; idx += 256) {
        int il = idx >> 4, q = idx & 15;
        float4 v = __ldg((const float4*)&g_ce[(size_t)(b * N_SZ + it * 64 + il) * 512 + h * 64 + q * 4]);
        *(float4*)&sCe[il * 64 + q * 4] = v;
    }
    __syncthreads();

    #pragma unroll
    for (int ii = 0; ii < 8; ii++) {
        int il = ti * 8 + ii;
        int ig = it * 64 + il;
        float a = 0.f;
        #pragma unroll
        for (int jq = 0; jq < 4; jq++)
            a += __ldg(&g_po[(((size_t)(b * HEADS + h) * 4 + jq) * N_SZ + ig) * DH + lane]);
        float dot = 0.f;
        #pragma unroll 8
        for (int dp = 0; dp < 64; dp++)
            dot += sCe[il * 64 + dp] * sWev[lane * 65 + dp];
        float inv = 1.f / __ldg(&g_ssum[(size_t)(b * N_SZ + ig) * HEADS + h]);
        out[(size_t)(b * N_SZ + ig) * NDIM + h * 32 + lane] = (dot + a) * inv;
    }
}

// =================================================================================
extern "C" void kernel_launch(void* const* d_in, const int* in_sizes, int n_in,
                              void* d_out, int out_size)
{
    const float* node = (const float*)d_in[0];
    const float* edge = (const float*)d_in[1];
    const float* Wnq  = (const float*)d_in[2];
    const float* bnq  = (const float*)d_in[3];
    const float* Wnk  = (const float*)d_in[4];
    const float* bnk  = (const float*)d_in[5];
    const float* Wnv  = (const float*)d_in[6];
    const float* bnv  = (const float*)d_in[7];
    const float* Weq  = (const float*)d_in[8];
    const float* beq  = (const float*)d_in[9];
    const float* Wek  = (const float*)d_in[10];
    const float* bek  = (const float*)d_in[11];
    const float* Wev  = (const float*)d_in[12];
    const float* bev  = (const float*)d_in[13];
    float* out = (float*)d_out;

    const int smemA = (32 * 257 + 64 * 260) * 4;     // 99456 B
    const int smemB = 22048 * 4;                     // 88192 B
    cudaFuncSetAttribute(node_proj_kernel, cudaFuncAttributeMaxDynamicSharedMemorySize, smemA);
    cudaFuncSetAttribute(attn_kernel, cudaFuncAttributeMaxDynamicSharedMemorySize, smemB);

    weight_frag_kernel<<<16, 256>>>(Weq, Wek);

    dim3 gridA(32, 3);
    node_proj_kernel<<<gridA, 256, smemA>>>(node, Wnq, bnq, Wnk, bnk, Wnv, bnv, beq, bek, bev);

    dim3 gridB(N_SZ, B_SZ);
    attn_kernel<<<gridB, 256, smemB>>>(edge);

    dim3 gridC1(32, HEADS, B_SZ);
    outp_kernel<<<gridC1, 256>>>();

    dim3 gridC2(8, HEADS, B_SZ);
    outr_kernel<<<gridC2, 256>>>(Wev, out);
}